// round 5
// baseline (speedup 1.0000x reference)
#include <cuda_runtime.h>

#define EPS  1e-6f
#define TPB  128
#define ROW  25            // padded row stride (floats): gcd(25,32)=1 -> conflict-free LDS
#define MAXG 2048

// Scratch (no device allocation allowed). Zero-initialized at module load.
// g_ticket self-resets via atomicInc wrap -> deterministic across graph replays.
__device__ float        g_psum[MAXG];
__device__ float        g_pcnt[MAXG];
__device__ unsigned int g_ticket;

__global__ void __launch_bounds__(TPB) gsc_fused(
    const float* __restrict__ pred, const float* __restrict__ gt,
    float* __restrict__ out, int B, int nTiles)
{
    __shared__ float sp[TPB * ROW];
    __shared__ float sg[TPB * ROW];
    __shared__ float swsum[4];
    __shared__ float swcnt[4];
    __shared__ int   s_last;

    const int tid = threadIdx.x;
    float accL = 0.f, accC = 0.f;

    const float4* p4 = reinterpret_cast<const float4*>(pred);
    const float4* g4 = reinterpret_cast<const float4*>(gt);

    for (int tile = blockIdx.x; tile < nTiles; tile += gridDim.x) {
        const int  base  = tile * TPB;              // first batch in tile
        const int  nB    = min(TPB, B - base);      // batches in this tile
        const int  n4    = nB * 6;                  // valid float4 count
        const long gbase = (long)base * 6;          // float4 offset

        // ---- stage: fully coalesced LDG.128, padded scatter into SMEM ----
#pragma unroll
        for (int i = 0; i < 6; ++i) {
            int idx = i * TPB + tid;
            float4 t = make_float4(0.f, 0.f, 0.f, 0.f);
            float4 u = make_float4(0.f, 0.f, 0.f, 0.f);
            if (idx < n4) { t = p4[gbase + idx]; u = g4[gbase + idx]; }
            int r = idx / 6, w = idx % 6;
            int a = r * ROW + w * 4;
            sp[a] = t.x; sp[a+1] = t.y; sp[a+2] = t.z; sp[a+3] = t.w;
            sg[a] = u.x; sg[a+1] = u.y; sg[a+2] = u.z; sg[a+3] = u.w;
        }
        __syncthreads();

        const float* rp = sp + tid * ROW;
        const float* rg = sg + tid * ROW;

        // ---- stable "first 4 visible" select, fully unrolled (no spills) ----
        float px[4] = {0,0,0,0}, py[4] = {0,0,0,0};
        float gx[4] = {0,0,0,0}, gy[4] = {0,0,0,0};
        int nv = 0;
#pragma unroll
        for (int k = 0; k < 8; ++k) {
            float pz = rp[3*k+2], gz = rg[3*k+2];
            bool vis = (pz > 0.5f) && (gz > 0.5f);
            float pxk = rp[3*k], pyk = rp[3*k+1];
            float gxk = rg[3*k], gyk = rg[3*k+1];
#pragma unroll
            for (int s = 0; s < 4; ++s) {
                if (vis && nv == s) {
                    px[s] = pxk; py[s] = pyk; gx[s] = gxk; gy[s] = gyk;
                }
            }
            nv += vis ? 1 : 0;
        }
        bool valid = (tid < nB) && (nv >= 4);

        // ---- L_shape ----
        float d31x = px[2]-px[0], d31y = py[2]-py[0];
        float d42x = px[3]-px[1], d42y = py[3]-py[1];
        float e31x = gx[2]-gx[0], e31y = gy[2]-gy[0];
        float e42x = gx[3]-gx[1], e42y = gy[3]-gy[1];
        float pcr = __fdividef(sqrtf(d31x*d31x + d31y*d31y),
                               sqrtf(d42x*d42x + d42y*d42y) + EPS);
        float gcr = __fdividef(sqrtf(e31x*e31x + e31y*e31y),
                               sqrtf(e42x*e42x + e42y*e42y) + EPS);
        float L_shape = fabsf(pcr - gcr);

        // ---- L_edge ----
        float v12x = px[1]-px[0], v12y = py[1]-py[0];
        float v23x = px[2]-px[1], v23y = py[2]-py[1];
        float v34x = px[3]-px[2], v34y = py[3]-py[2];
        float v41x = px[0]-px[3], v41y = py[0]-py[3];
        float l12 = sqrtf(v12x*v12x + v12y*v12y);
        float l23 = sqrtf(v23x*v23x + v23y*v23y);
        float l34 = sqrtf(v34x*v34x + v34y*v34y);
        float l41 = sqrtf(v41x*v41x + v41y*v41y);
        float par1 = __fdividef(fabsf(l12 - l34), l12 + l34 + EPS);
        float par2 = __fdividef(fabsf(l23 - l41), l23 + l41 + EPS);
        float dot1 = fabsf(__fdividef(v12x*v41x + v12y*v41y, l12*l41 + EPS));
        float dot2 = fabsf(__fdividef(v12x*v23x + v12y*v23y, l12*l23 + EPS));
        float dot3 = fabsf(__fdividef(v23x*v34x + v23y*v34y, l23*l34 + EPS));
        float dot4 = fabsf(__fdividef(v34x*v41x + v34y*v41y, l34*l41 + EPS));
        float L_edge = 0.5f*(par1 + par2) + 0.25f*(dot1 + dot2 + dot3 + dot4);

        // ---- L_pos ----
        float dist = 0.f;
#pragma unroll
        for (int i = 0; i < 4; ++i) {
            float dx = px[i]-gx[i], dy = py[i]-gy[i];
            dist += sqrtf(dx*dx + dy*dy);
        }
        dist *= 0.25f;

        float d41x = px[3]-px[0], d41y = py[3]-py[0];
        float parea = 0.5f * (fabsf(v12x*d31y - v12y*d31x) +
                              fabsf(d31x*d41y - d31y*d41x));
        float w12x = gx[1]-gx[0], w12y = gy[1]-gy[0];
        float e41x = gx[3]-gx[0], e41y = gy[3]-gy[0];
        float garea = 0.5f * (fabsf(w12x*e31y - w12y*e31x) +
                              fabsf(e31x*e41y - e31y*e41x));
        float area_ratio = __fdividef(fabsf(parea - garea), garea + EPS);

        float dmx = 0.25f*((px[0]-gx[0]) + (px[1]-gx[1]) + (px[2]-gx[2]) + (px[3]-gx[3]));
        float dmy = 0.25f*((py[0]-gy[0]) + (py[1]-gy[1]) + (py[2]-gy[2]) + (py[3]-gy[3]));
        float rel = 0.f;
#pragma unroll
        for (int i = 0; i < 4; ++i) {
            float dx = (px[i]-gx[i]) - dmx;
            float dy = (py[i]-gy[i]) - dmy;
            rel += sqrtf(dx*dx + dy*dy);
        }
        rel *= 0.25f;

        float L_pos = 0.4f*dist + 0.3f*area_ratio + 0.3f*rel;
        float L     = 0.4f*L_shape + 0.3f*L_edge + 0.3f*L_pos;

        accL += valid ? L   : 0.f;
        accC += valid ? 1.f : 0.f;

        __syncthreads();   // protect SMEM before next tile's staging
    }

    // ---- block reduction ----
    int lane = tid & 31, wid = tid >> 5;
#pragma unroll
    for (int off = 16; off > 0; off >>= 1) {
        accL += __shfl_down_sync(0xffffffffu, accL, off);
        accC += __shfl_down_sync(0xffffffffu, accC, off);
    }
    if (lane == 0) { swsum[wid] = accL; swcnt[wid] = accC; }
    __syncthreads();
    if (tid == 0) {
        float bs = swsum[0] + swsum[1] + swsum[2] + swsum[3];
        float bc = swcnt[0] + swcnt[1] + swcnt[2] + swcnt[3];
        g_psum[blockIdx.x] = bs;
        g_pcnt[blockIdx.x] = bc;
        __threadfence();
        unsigned int t = atomicInc(&g_ticket, gridDim.x - 1); // wraps to 0 -> replay-safe
        s_last = (t == gridDim.x - 1) ? 1 : 0;
    }
    __syncthreads();

    // ---- last block finalizes ----
    if (s_last) {
        __threadfence();
        double s = 0.0; float c = 0.f;
        for (int i = tid; i < gridDim.x; i += TPB) {
            s += (double)g_psum[i];
            c += g_pcnt[i];
        }
#pragma unroll
        for (int off = 16; off > 0; off >>= 1) {
            s += __shfl_down_sync(0xffffffffu, s, off);
            c += __shfl_down_sync(0xffffffffu, c, off);
        }
        __shared__ double sds[4];
        __shared__ float  sdc[4];
        if (lane == 0) { sds[wid] = s; sdc[wid] = c; }
        __syncthreads();
        if (tid == 0) {
            double ts = sds[0] + sds[1] + sds[2] + sds[3];
            float  tc = sdc[0] + sdc[1] + sdc[2] + sdc[3];
            out[0] = (tc > 0.f) ? (float)(ts / (double)tc) : 0.f;
        }
    }
}

extern "C" void kernel_launch(void* const* d_in, const int* in_sizes, int n_in,
                              void* d_out, int out_size)
{
    const float* pred = (const float*)d_in[0];
    const float* gt   = (const float*)d_in[1];
    int B = in_sizes[0] / 24;          // [B, 8, 3] float32
    int nTiles = (B + TPB - 1) / TPB;
    int grid = nTiles < MAXG ? nTiles : MAXG;

    gsc_fused<<<grid, TPB>>>(pred, gt, (float*)d_out, B, nTiles);
}